// round 6
// baseline (speedup 1.0000x reference)
#include <cuda_runtime.h>
#include <cuda_bf16.h>
#include <stdint.h>

// Problem constants (fixed by the dataset).
#define Nn 20000
#define Ee 5000
#define Ff 128
#define NODE_CAP 256   // max edges per node (Binom(5000,.01): mean 50, max ~81)
#define EDGE_CAP 512   // max nodes per edge (Binom(20000,.01): mean 200, max ~260)
#define XW_BLOCKS (Nn / 32)   // 625

// ---------------- device scratch (no allocations allowed) ----------------
__device__ __nv_bfloat16 g_Xw[Nn * Ff];   // 5.12 MB (L2-resident)
__device__ __nv_bfloat16 g_M[Ee * Ff];    // 1.28 MB (L2-resident)
__device__ int   g_node_cnt[Nn];
__device__ int   g_edge_cnt[Ee];
__device__ unsigned short g_node_edges[Nn * NODE_CAP];
__device__ unsigned short g_edge_nodes[Ee * EDGE_CAP];

// fp32 accumulate of 4 bf16 packed in uint2
__device__ __forceinline__ void acc_bf16x4(float4& a, uint2 p) {
    __nv_bfloat162 lo = *reinterpret_cast<__nv_bfloat162*>(&p.x);
    __nv_bfloat162 hi = *reinterpret_cast<__nv_bfloat162*>(&p.y);
    float2 flo = __bfloat1622float2(lo);
    float2 fhi = __bfloat1622float2(hi);
    a.x += flo.x; a.y += flo.y; a.z += fhi.x; a.w += fhi.y;
}

__device__ __forceinline__ uint2 f4_to_bf16x4(float4 a) {
    __nv_bfloat162 lo = __floats2bfloat162_rn(a.x, a.y);
    __nv_bfloat162 hi = __floats2bfloat162_rn(a.z, a.w);
    uint2 r;
    r.x = *reinterpret_cast<unsigned*>(&lo);
    r.y = *reinterpret_cast<unsigned*>(&hi);
    return r;
}

// ---------------- K0: zero the edge counters only ----------------
__global__ void k_zero_counters() {
    int i = blockIdx.x * blockDim.x + threadIdx.x;
    if (i < Ee) g_edge_cnt[i] = 0;
}

// ---------------- K1 (fused): blocks [0,625) do Xw=X@W; rest scan H ------
__global__ __launch_bounds__(256) void k_xw_scan(const float* __restrict__ X,
                                                 const float* __restrict__ W,
                                                 const float* __restrict__ H) {
    int tid = threadIdx.x;

    if (blockIdx.x < XW_BLOCKS) {
        // ---- GEMM part: 32-row x 128-col tile, 4x4 register micro-tile ----
        __shared__ float xs[32][Ff];   // 16 KB
        int tx = tid & 31;             // col group
        int ty = tid >> 5;             // row group
        int row0 = blockIdx.x * 32;

        const float4* X4 = (const float4*)(X + (size_t)row0 * Ff);
#pragma unroll
        for (int k = 0; k < 4; k++) {
            int v = tid + k * 256;
            int r = v >> 5, c4 = v & 31;
            ((float4*)&xs[r][0])[c4] = X4[r * 32 + c4];
        }
        __syncthreads();

        const float4* W4 = (const float4*)W;
        float4 acc0 = {0,0,0,0}, acc1 = {0,0,0,0}, acc2 = {0,0,0,0}, acc3 = {0,0,0,0};
        int r0 = 4 * ty;

#pragma unroll 4
        for (int k = 0; k < Ff; k++) {
            float4 w = W4[k * 32 + tx];
            float x0 = xs[r0 + 0][k];
            float x1 = xs[r0 + 1][k];
            float x2 = xs[r0 + 2][k];
            float x3 = xs[r0 + 3][k];
            acc0.x += x0 * w.x; acc0.y += x0 * w.y; acc0.z += x0 * w.z; acc0.w += x0 * w.w;
            acc1.x += x1 * w.x; acc1.y += x1 * w.y; acc1.z += x1 * w.z; acc1.w += x1 * w.w;
            acc2.x += x2 * w.x; acc2.y += x2 * w.y; acc2.z += x2 * w.z; acc2.w += x2 * w.w;
            acc3.x += x3 * w.x; acc3.y += x3 * w.y; acc3.z += x3 * w.z; acc3.w += x3 * w.w;
        }

        uint2* O2 = (uint2*)g_Xw;   // row stride 32 uint2 (256 B)
        int orow = row0 + r0;
        O2[(orow + 0) * 32 + tx] = f4_to_bf16x4(acc0);
        O2[(orow + 1) * 32 + tx] = f4_to_bf16x4(acc1);
        O2[(orow + 2) * 32 + tx] = f4_to_bf16x4(acc2);
        O2[(orow + 3) * 32 + tx] = f4_to_bf16x4(acc3);
    } else {
        // ---- Scan part: one block per node row; H entries exactly 0/1 ----
        __shared__ int s_cnt;
        int n = blockIdx.x - XW_BLOCKS;
        if (tid == 0) s_cnt = 0;
        __syncthreads();

        const uint4* row = (const uint4*)(H + (size_t)n * Ee);
        const int nvec = Ee / 4;  // 1250
        for (int i4 = tid; i4 < nvec; i4 += 256) {
            uint4 v = row[i4];
            unsigned vals[4] = {v.x, v.y, v.z, v.w};
#pragma unroll
            for (int c = 0; c < 4; c++) {
                if (vals[c] != 0u) {
                    int e = i4 * 4 + c;
                    int j = atomicAdd(&s_cnt, 1);
                    if (j < NODE_CAP) g_node_edges[n * NODE_CAP + j] = (unsigned short)e;
                    int k = atomicAdd(&g_edge_cnt[e], 1);
                    if (k < EDGE_CAP) g_edge_nodes[e * EDGE_CAP + k] = (unsigned short)n;
                }
            }
        }
        __syncthreads();
        if (tid == 0) g_node_cnt[n] = s_cnt;
    }
}

// ---------------- K3: block-per-edge, 4 warps, 8-deep MLP, bf16 loads ----
__global__ __launch_bounds__(128) void k_edge_gather() {
    __shared__ unsigned short s_list[EDGE_CAP];
    __shared__ float4 s_red[4][32];
    int e = blockIdx.x;
    int tid = threadIdx.x;
    int w = tid >> 5, l = tid & 31;
    int cnt = g_edge_cnt[e];
    int L = cnt < EDGE_CAP ? cnt : EDGE_CAP;
    for (int i = tid; i < L; i += 128)
        s_list[i] = g_edge_nodes[e * EDGE_CAP + i];
    __syncthreads();

    const uint2* Xw2 = (const uint2*)g_Xw;   // row stride 32 uint2
    float4 a[8];
#pragma unroll
    for (int u = 0; u < 8; u++) a[u] = make_float4(0.f, 0.f, 0.f, 0.f);

    int i = w;
    for (; i + 28 < L; i += 32) {
#pragma unroll
        for (int u = 0; u < 8; u++) {
            int n = s_list[i + 4 * u];
            acc_bf16x4(a[u], __ldg(&Xw2[n * 32 + l]));
        }
    }
    for (; i < L; i += 4)
        acc_bf16x4(a[0], __ldg(&Xw2[(int)s_list[i] * 32 + l]));

#pragma unroll
    for (int u = 1; u < 8; u++) {
        a[0].x += a[u].x; a[0].y += a[u].y; a[0].z += a[u].z; a[0].w += a[u].w;
    }
    s_red[w][l] = a[0];
    __syncthreads();

    if (w == 0) {
        float4 s = s_red[0][l];
        float4 s1 = s_red[1][l], s2 = s_red[2][l], s3 = s_red[3][l];
        s.x += s1.x + s2.x + s3.x;
        s.y += s1.y + s2.y + s3.y;
        s.z += s1.z + s2.z + s3.z;
        s.w += s1.w + s2.w + s3.w;
        float inv = __fdividef(1.0f, (float)cnt + 1e-12f);
        s.x *= inv; s.y *= inv; s.z *= inv; s.w *= inv;
        ((uint2*)g_M)[e * 32 + l] = f4_to_bf16x4(s);
    }
}

// ---------------- K4: block-per-node, 4 warps, bf16 loads, fp32 out ------
__global__ __launch_bounds__(128) void k_node_gather(const float* __restrict__ bias,
                                                     float* __restrict__ out) {
    __shared__ unsigned short s_list[NODE_CAP];
    __shared__ float4 s_red[4][32];
    int n = blockIdx.x;
    int tid = threadIdx.x;
    int w = tid >> 5, l = tid & 31;
    int cnt = g_node_cnt[n];
    int L = cnt < NODE_CAP ? cnt : NODE_CAP;
    for (int i = tid; i < L; i += 128)
        s_list[i] = g_node_edges[n * NODE_CAP + i];
    __syncthreads();

    const uint2* M2 = (const uint2*)g_M;   // row stride 32 uint2
    float4 a[4];
#pragma unroll
    for (int u = 0; u < 4; u++) a[u] = make_float4(0.f, 0.f, 0.f, 0.f);

    int i = w;
    for (; i + 12 < L; i += 16) {
#pragma unroll
        for (int u = 0; u < 4; u++) {
            int e = s_list[i + 4 * u];
            acc_bf16x4(a[u], __ldg(&M2[e * 32 + l]));
        }
    }
    for (; i < L; i += 4)
        acc_bf16x4(a[0], __ldg(&M2[(int)s_list[i] * 32 + l]));

#pragma unroll
    for (int u = 1; u < 4; u++) {
        a[0].x += a[u].x; a[0].y += a[u].y; a[0].z += a[u].z; a[0].w += a[u].w;
    }
    s_red[w][l] = a[0];
    __syncthreads();

    if (w == 0) {
        float4 r = s_red[0][l];
        float4 s1 = s_red[1][l], s2 = s_red[2][l], s3 = s_red[3][l];
        r.x += s1.x + s2.x + s3.x;
        r.y += s1.y + s2.y + s3.y;
        r.z += s1.z + s2.z + s3.z;
        r.w += s1.w + s2.w + s3.w;
        float inv = __fdividef(1.0f, (float)cnt + 1e-12f);
        float4 b = ((const float4*)bias)[l];
        r.x = fmaxf(r.x * inv + b.x, 0.0f);
        r.y = fmaxf(r.y * inv + b.y, 0.0f);
        r.z = fmaxf(r.z * inv + b.z, 0.0f);
        r.w = fmaxf(r.w * inv + b.w, 0.0f);
        ((float4*)out)[n * 32 + l] = r;
    }
}

// ---------------- launch -------------------------------------------------
extern "C" void kernel_launch(void* const* d_in, const int* in_sizes, int n_in,
                              void* d_out, int out_size) {
    const float* X = (const float*)d_in[0];
    const float* H = (const float*)d_in[1];
    const float* W = (const float*)d_in[2];
    const float* bias = (const float*)d_in[3];
    float* out = (float*)d_out;

    k_zero_counters<<<(Ee + 255) / 256, 256>>>();
    k_xw_scan<<<XW_BLOCKS + Nn, 256>>>(X, W, H);
    k_edge_gather<<<Ee, 128>>>();
    k_node_gather<<<Nn, 128>>>(bias, out);
}

// round 7
// speedup vs baseline: 1.3409x; 1.3409x over previous
#include <cuda_runtime.h>
#include <stdint.h>

// Problem constants (fixed by the dataset).
#define Nn 20000
#define Ee 5000
#define Ff 128
#define NODE_CAP 256   // max edges per node (Binom(5000,.01): mean 50, max ~81)
#define EDGE_CAP 512   // max nodes per edge (Binom(20000,.01): mean 200, max ~260)

// ---------------- device scratch (no allocations allowed) ----------------
__device__ float g_Xw[Nn * Ff];                        // 10.24 MB (L2-resident)
__device__ float g_M[Ee * Ff];                         //  2.56 MB (L2-resident)
__device__ int   g_node_cnt[Nn];
__device__ int   g_edge_cnt[Ee];
__device__ unsigned short g_node_edges[Nn * NODE_CAP];
__device__ unsigned short g_edge_nodes[Ee * EDGE_CAP];

__device__ __forceinline__ float4 f4add(float4 a, float4 b) {
    a.x += b.x; a.y += b.y; a.z += b.z; a.w += b.w; return a;
}

// ---------------- K0: zero the edge counters only ----------------
__global__ void k_zero_counters() {
    int i = blockIdx.x * blockDim.x + threadIdx.x;
    if (i < Ee) g_edge_cnt[i] = 0;
}

// ---------------- K1: Xw = X @ W, 4x4 register micro-tile ----------------
__global__ __launch_bounds__(256) void k_xw(const float* __restrict__ X,
                                            const float* __restrict__ W) {
    __shared__ float xs[32][Ff];   // 16 KB X tile
    int tx = threadIdx.x;          // 0..31 (col group)
    int ty = threadIdx.y;          // 0..7  (row group)
    int tid = ty * 32 + tx;
    int row0 = blockIdx.x * 32;

    const float4* X4 = (const float4*)(X + (size_t)row0 * Ff);
#pragma unroll
    for (int k = 0; k < 4; k++) {
        int v = tid + k * 256;
        int r = v >> 5, c4 = v & 31;
        ((float4*)&xs[r][0])[c4] = X4[r * 32 + c4];
    }
    __syncthreads();

    const float4* W4 = (const float4*)W;
    float4 acc0 = {0,0,0,0}, acc1 = {0,0,0,0}, acc2 = {0,0,0,0}, acc3 = {0,0,0,0};
    int r0 = 4 * ty;

#pragma unroll 4
    for (int k = 0; k < Ff; k++) {
        float4 w = W4[k * 32 + tx];
        float x0 = xs[r0 + 0][k];
        float x1 = xs[r0 + 1][k];
        float x2 = xs[r0 + 2][k];
        float x3 = xs[r0 + 3][k];
        acc0.x += x0 * w.x; acc0.y += x0 * w.y; acc0.z += x0 * w.z; acc0.w += x0 * w.w;
        acc1.x += x1 * w.x; acc1.y += x1 * w.y; acc1.z += x1 * w.z; acc1.w += x1 * w.w;
        acc2.x += x2 * w.x; acc2.y += x2 * w.y; acc2.z += x2 * w.z; acc2.w += x2 * w.w;
        acc3.x += x3 * w.x; acc3.y += x3 * w.y; acc3.z += x3 * w.z; acc3.w += x3 * w.w;
    }

    float4* O4 = (float4*)g_Xw;
    int orow = row0 + r0;
    O4[(orow + 0) * 32 + tx] = acc0;
    O4[(orow + 1) * 32 + tx] = acc1;
    O4[(orow + 2) * 32 + tx] = acc2;
    O4[(orow + 3) * 32 + tx] = acc3;
}

// ---------------- K2: scan H with front-batched loads (MLP=5) ------------
// One block per node row. Each thread unconditionally preloads its 5 uint4
// (independent LDG.128s issue back-to-back), then processes from registers.
// H entries are exactly 0.0f or 1.0f -> integer compare is exact.
__global__ __launch_bounds__(256) void k_scan_h(const float* __restrict__ H) {
    __shared__ int s_cnt;
    int n = blockIdx.x;
    int tid = threadIdx.x;
    if (tid == 0) s_cnt = 0;
    __syncthreads();

    const uint4* row = (const uint4*)(H + (size_t)n * Ee);
    const int nvec = Ee / 4;  // 1250

    uint4 v[5];
#pragma unroll
    for (int k = 0; k < 5; k++) {
        int i = tid + k * 256;
        v[k] = (i < nvec) ? row[i] : make_uint4(0u, 0u, 0u, 0u);
    }

#pragma unroll
    for (int k = 0; k < 5; k++) {
        int i4 = tid + k * 256;
        unsigned vals[4] = {v[k].x, v[k].y, v[k].z, v[k].w};
#pragma unroll
        for (int c = 0; c < 4; c++) {
            if (vals[c] != 0u) {
                int e = i4 * 4 + c;
                int j = atomicAdd(&s_cnt, 1);
                if (j < NODE_CAP) g_node_edges[n * NODE_CAP + j] = (unsigned short)e;
                int kk = atomicAdd(&g_edge_cnt[e], 1);
                if (kk < EDGE_CAP) g_edge_nodes[e * EDGE_CAP + kk] = (unsigned short)n;
            }
        }
    }
    __syncthreads();
    if (tid == 0) g_node_cnt[n] = s_cnt;
}

// ---------------- K3: block-per-edge, 4 warps (R2-proven shape) ----------
__global__ __launch_bounds__(128) void k_edge_gather() {
    __shared__ unsigned short s_list[EDGE_CAP];
    __shared__ float4 s_red[4][32];
    int e = blockIdx.x;
    int tid = threadIdx.x;
    int w = tid >> 5, l = tid & 31;
    int cnt = g_edge_cnt[e];
    int L = cnt < EDGE_CAP ? cnt : EDGE_CAP;
    for (int i = tid; i < L; i += 128)
        s_list[i] = g_edge_nodes[e * EDGE_CAP + i];
    __syncthreads();

    const float4* Xw4 = (const float4*)g_Xw;   // row stride 32
    float4 a0 = {0,0,0,0}, a1 = {0,0,0,0}, a2 = {0,0,0,0}, a3 = {0,0,0,0};
    int i = w;
    for (; i + 12 < L; i += 16) {
        int n0 = s_list[i], n1 = s_list[i + 4], n2 = s_list[i + 8], n3 = s_list[i + 12];
        a0 = f4add(a0, Xw4[n0 * 32 + l]);
        a1 = f4add(a1, Xw4[n1 * 32 + l]);
        a2 = f4add(a2, Xw4[n2 * 32 + l]);
        a3 = f4add(a3, Xw4[n3 * 32 + l]);
    }
    for (; i < L; i += 4)
        a0 = f4add(a0, Xw4[(int)s_list[i] * 32 + l]);

    s_red[w][l] = f4add(f4add(a0, a1), f4add(a2, a3));
    __syncthreads();

    if (w == 0) {
        float4 r = f4add(f4add(s_red[0][l], s_red[1][l]),
                         f4add(s_red[2][l], s_red[3][l]));
        float inv = __fdividef(1.0f, (float)cnt + 1e-12f);
        r.x *= inv; r.y *= inv; r.z *= inv; r.w *= inv;
        ((float4*)g_M)[e * 32 + l] = r;
    }
}

// ---------------- K4: block-per-node, 4 warps (R2-proven shape) ----------
__global__ __launch_bounds__(128) void k_node_gather(const float* __restrict__ bias,
                                                     float* __restrict__ out) {
    __shared__ unsigned short s_list[NODE_CAP];
    __shared__ float4 s_red[4][32];
    int n = blockIdx.x;
    int tid = threadIdx.x;
    int w = tid >> 5, l = tid & 31;
    int cnt = g_node_cnt[n];
    int L = cnt < NODE_CAP ? cnt : NODE_CAP;
    for (int i = tid; i < L; i += 128)
        s_list[i] = g_node_edges[n * NODE_CAP + i];
    __syncthreads();

    const float4* M4 = (const float4*)g_M;   // row stride 32
    float4 a0 = {0,0,0,0}, a1 = {0,0,0,0}, a2 = {0,0,0,0}, a3 = {0,0,0,0};
    int i = w;
    for (; i + 12 < L; i += 16) {
        int e0 = s_list[i], e1 = s_list[i + 4], e2 = s_list[i + 8], e3 = s_list[i + 12];
        a0 = f4add(a0, M4[e0 * 32 + l]);
        a1 = f4add(a1, M4[e1 * 32 + l]);
        a2 = f4add(a2, M4[e2 * 32 + l]);
        a3 = f4add(a3, M4[e3 * 32 + l]);
    }
    for (; i < L; i += 4)
        a0 = f4add(a0, M4[(int)s_list[i] * 32 + l]);

    s_red[w][l] = f4add(f4add(a0, a1), f4add(a2, a3));
    __syncthreads();

    if (w == 0) {
        float4 r = f4add(f4add(s_red[0][l], s_red[1][l]),
                         f4add(s_red[2][l], s_red[3][l]));
        float inv = __fdividef(1.0f, (float)cnt + 1e-12f);
        float4 b = ((const float4*)bias)[l];
        r.x = fmaxf(r.x * inv + b.x, 0.0f);
        r.y = fmaxf(r.y * inv + b.y, 0.0f);
        r.z = fmaxf(r.z * inv + b.z, 0.0f);
        r.w = fmaxf(r.w * inv + b.w, 0.0f);
        ((float4*)out)[n * 32 + l] = r;
    }
}

// ---------------- launch -------------------------------------------------
extern "C" void kernel_launch(void* const* d_in, const int* in_sizes, int n_in,
                              void* d_out, int out_size) {
    const float* X = (const float*)d_in[0];
    const float* H = (const float*)d_in[1];
    const float* W = (const float*)d_in[2];
    const float* bias = (const float*)d_in[3];
    float* out = (float*)d_out;

    k_zero_counters<<<(Ee + 255) / 256, 256>>>();
    dim3 xwb(32, 8);
    k_xw<<<Nn / 32, xwb>>>(X, W);
    // Probe launch: harmless re-zero (scan hasn't run yet) so that k_scan_h
    // lands in the profiled (4th) launch slot this round.
    k_zero_counters<<<(Ee + 255) / 256, 256>>>();
    k_scan_h<<<Nn, 256>>>(H);
    k_edge_gather<<<Ee, 128>>>();
    k_node_gather<<<Nn, 128>>>(bias, out);
}